// round 8
// baseline (speedup 1.0000x reference)
#include <cuda_runtime.h>
#include <cuda_fp16.h>
#include <cstdint>

#define B_   16
#define C_   512
#define HW_  4096
#define W64  64
#define WD_  512
#define EPS_ 1e-6f
#define NT_  16384           // total Winograd tiles = B_ * 1024
#define NCF  16              // Winograd coefficients (4x4)

// ---------------- scratch (__device__ globals; no runtime alloc) ----------------
__device__ float  g_style[B_ * C_];
__device__ float  g_S[C_ * C_];
__device__ float  g_rdenom[B_ * C_];
__device__ __half g_U[(size_t)NCF * C_ * C_];        // (coef, oc, ic) fp16
__device__ __half g_V[(size_t)NCF * NT_ * C_];       // (coef, n, ic)  fp16

// ---------------- helpers ----------------
__device__ __forceinline__ uint32_t smem_u32(const void* p) {
    uint32_t a;
    asm("{ .reg .u64 t; cvta.to.shared.u64 t, %1; cvt.u32.u64 %0, t; }" : "=r"(a) : "l"(p));
    return a;
}
__device__ __forceinline__ void cp16(uint32_t dst, const void* src) {
    asm volatile("cp.async.cg.shared.global [%0], [%1], 16;" :: "r"(dst), "l"(src));
}
template <int N>
__device__ __forceinline__ void cp_wait() {
    asm volatile("cp.async.wait_group %0;" :: "n"(N) : "memory");
}
__device__ __forceinline__ void cp_commit() {
    asm volatile("cp.async.commit_group;" ::: "memory");
}
__device__ __forceinline__ void ldsm4(uint32_t* r, uint32_t addr) {
    asm volatile("ldmatrix.sync.aligned.m8n8.x4.shared.b16 {%0,%1,%2,%3}, [%4];"
                 : "=r"(r[0]), "=r"(r[1]), "=r"(r[2]), "=r"(r[3]) : "r"(addr));
}
__device__ __forceinline__ void mma_f16(float* d, const uint32_t* a, const uint32_t* bf) {
    asm volatile(
        "mma.sync.aligned.m16n8k16.row.col.f32.f16.f16.f32 "
        "{%0,%1,%2,%3}, {%4,%5,%6,%7}, {%8,%9}, {%0,%1,%2,%3};"
        : "+f"(d[0]), "+f"(d[1]), "+f"(d[2]), "+f"(d[3])
        : "r"(a[0]), "r"(a[1]), "r"(a[2]), "r"(a[3]), "r"(bf[0]), "r"(bf[1]));
}

// ---------------- prologue: style / S / rdenom ----------------
__global__ void style_kernel(const float* __restrict__ w, const float* __restrict__ lw,
                             const float* __restrict__ lb) {
    __shared__ float ws[WD_];
    int b = blockIdx.x, o = threadIdx.x;
    ws[o] = w[b * WD_ + o];
    __syncthreads();
    const float* lwr = lw + (size_t)o * WD_;
    float acc = lb[o];
#pragma unroll 8
    for (int d = 0; d < WD_; d++) acc = fmaf(ws[d], lwr[d], acc);
    g_style[b * C_ + o] = acc;
}

__global__ void s_kernel(const float* __restrict__ cw) {
    int o = blockIdx.x, i = threadIdx.x;
    const float* p = cw + ((size_t)o * C_ + i) * 9;
    float s = 0.f;
#pragma unroll
    for (int k = 0; k < 9; k++) { float v = p[k]; s = fmaf(v, v, s); }
    g_S[o * C_ + i] = s;
}

__global__ void rdenom_kernel() {
    __shared__ float st2[C_];
    int b = blockIdx.x, o = threadIdx.x;
    float s = g_style[b * C_ + o];
    st2[o] = s * s;
    __syncthreads();
    const float* Sr = g_S + (size_t)o * C_;
    float acc = EPS_;
#pragma unroll 8
    for (int i = 0; i < C_; i++) acc = fmaf(Sr[i], st2[i], acc);
    g_rdenom[b * C_ + o] = rsqrtf(acc);
}

// ---------------- Winograd weight transform: U = G g G^T ----------------
__global__ void wino_w_kernel(const float* __restrict__ cw) {
    int o = blockIdx.x, i = threadIdx.x;
    const float* g = cw + ((size_t)o * C_ + i) * 9;
    float q[3][3];
#pragma unroll
    for (int r = 0; r < 3; r++)
#pragma unroll
        for (int c = 0; c < 3; c++) q[r][c] = g[r * 3 + c];
    float t[4][3];
#pragma unroll
    for (int c = 0; c < 3; c++) {
        t[0][c] = q[0][c];
        t[1][c] = 0.5f * (q[0][c] + q[1][c] + q[2][c]);
        t[2][c] = 0.5f * (q[0][c] - q[1][c] + q[2][c]);
        t[3][c] = q[2][c];
    }
#pragma unroll
    for (int r = 0; r < 4; r++) {
        float u0 = t[r][0];
        float u1 = 0.5f * (t[r][0] + t[r][1] + t[r][2]);
        float u2 = 0.5f * (t[r][0] - t[r][1] + t[r][2]);
        float u3 = t[r][2];
        g_U[((size_t)(r * 4 + 0) * C_ + o) * C_ + i] = __float2half_rn(u0);
        g_U[((size_t)(r * 4 + 1) * C_ + o) * C_ + i] = __float2half_rn(u1);
        g_U[((size_t)(r * 4 + 2) * C_ + o) * C_ + i] = __float2half_rn(u2);
        g_U[((size_t)(r * 4 + 3) * C_ + o) * C_ + i] = __float2half_rn(u3);
    }
}

// ---------------- Winograd input transform: V = B^T d B (style folded) ----------------
__global__ void __launch_bounds__(256)
wino_x_kernel(const float* __restrict__ x) {
    __shared__ float xs[4][32][71];
    const int b = blockIdx.z, chg = blockIdx.y * 32, ty = blockIdx.x;
    const int tid = threadIdx.x;

    for (int idx = tid; idx < 4 * 32 * 68; idx += 256) {
        int r   = idx / (32 * 68);
        int rem = idx % (32 * 68);
        int ch  = rem / 68;
        int col = rem % 68;
        if (col < 66) {
            int y  = ty * 2 - 1 + r;
            int xg = col - 1;
            float v = 0.f;
            if ((unsigned)y < W64 && (unsigned)xg < W64)
                v = x[((size_t)(b * C_ + chg + ch)) * HW_ + y * W64 + xg];
            xs[r][ch][col] = v;
        }
    }
    __syncthreads();

    const int tx  = tid >> 3;          // 0..31 tile col
    const int ch4 = (tid & 7) * 4;     // 0,4,...,28
    const int n   = b * 1024 + ty * 32 + tx;

    unsigned short hs[NCF][4];
#pragma unroll
    for (int cc = 0; cc < 4; cc++) {
        const int ch = ch4 + cc;
        const float st = g_style[b * C_ + chg + ch];
        float d[4][4];
#pragma unroll
        for (int r = 0; r < 4; r++)
#pragma unroll
            for (int c = 0; c < 4; c++) d[r][c] = xs[r][ch][2 * tx + c];
        float wv[4][4];
#pragma unroll
        for (int c = 0; c < 4; c++) {
            wv[0][c] = d[0][c] - d[2][c];
            wv[1][c] = d[1][c] + d[2][c];
            wv[2][c] = d[2][c] - d[1][c];
            wv[3][c] = d[1][c] - d[3][c];
        }
#pragma unroll
        for (int r = 0; r < 4; r++) {
            float v0 = wv[r][0] - wv[r][2];
            float v1 = wv[r][1] + wv[r][2];
            float v2 = wv[r][2] - wv[r][1];
            float v3 = wv[r][1] - wv[r][3];
            hs[r * 4 + 0][cc] = __half_as_ushort(__float2half_rn(v0 * st));
            hs[r * 4 + 1][cc] = __half_as_ushort(__float2half_rn(v1 * st));
            hs[r * 4 + 2][cc] = __half_as_ushort(__float2half_rn(v2 * st));
            hs[r * 4 + 3][cc] = __half_as_ushort(__float2half_rn(v3 * st));
        }
    }
#pragma unroll
    for (int c = 0; c < NCF; c++) {
        uint2 val;
        val.x = (uint32_t)hs[c][0] | ((uint32_t)hs[c][1] << 16);
        val.y = (uint32_t)hs[c][2] | ((uint32_t)hs[c][3] << 16);
        *(uint2*)(g_V + ((size_t)c * NT_ + n) * C_ + chg + ch4) = val;
    }
}

// ---------------- fused GEMM (16 coefs) + inverse transform + demodulate ----------------
// CTA: 128 oc x 64 tiles. coef = 0..15 GEMMs (K=512, 16 chunks of 32ch) run through
// ONE continuous 256-iteration cp.async pipeline; after each coef, fold acc into
// 4 persistent y accumulators with A^T weights. 8 warps: (wm 2)x(wn 4); warp tile
// 64oc x 16n = 4x2 m16n8k16 tiles x 2 ksteps. One __syncthreads per iteration.
#define STR     40                          // halves per row (80B)
#define A_TILE_H (128 * STR)                // 5120 halves
#define B_TILE_H (64 * STR)                 // 2560 halves
#define STAGE_B ((A_TILE_H + B_TILE_H) * 2) // 15360 bytes
#define NSTAGE  4
#define SMEM_BYTES (NSTAGE * STAGE_B)       // 61440

__global__ void __launch_bounds__(256, 1)
wino_fused_kernel(float* __restrict__ out) {
    extern __shared__ __half smh[];
    const int tid  = threadIdx.x;
    const int oc0  = blockIdx.x * 128;     // oc fastest -> V tile shared in L2
    const int n0   = blockIdx.y * 64;
    const int lane = tid & 31;
    const int wrp  = tid >> 5;
    const int wm   = wrp & 1;              // 0..1 -> 64-row block
    const int wn   = wrp >> 1;             // 0..3 -> 16-col block
    const int qr   = lane >> 2;            // 0..7
    const int qc   = lane & 3;             // 0..3
    const int fr   = tid >> 2;             // 0..63 fill row
    const int fch  = (tid & 3) * 8;        // fill half-offset in 32-ch chunk

    const uint32_t sbase = smem_u32(smh);

    float acc[32];                          // current coef (4mt x 2nt x 4)
    float y00[32], y01[32], y10[32], y11[32];
#pragma unroll
    for (int i = 0; i < 32; i++) {
        acc[i] = 0.f; y00[i] = 0.f; y01[i] = 0.f; y10[i] = 0.f; y11[i] = 0.f;
    }

    auto issue = [&](int it) {
        const int s    = it & (NSTAGE - 1);
        const int coef = it >> 4;
        const int ci0  = (it & 15) << 5;
        const uint32_t stA = sbase + (uint32_t)s * STAGE_B;
        const uint32_t stB = stA + A_TILE_H * 2;
        const __half* Ab = g_U + ((size_t)coef * C_ + oc0 + fr) * C_ + ci0 + fch;
        const __half* Bb = g_V + ((size_t)coef * NT_ + n0 + fr) * C_ + ci0 + fch;
        cp16(stA + (uint32_t)(fr * STR + fch) * 2, Ab);
        cp16(stA + (uint32_t)((fr + 64) * STR + fch) * 2, Ab + (size_t)64 * C_);
        cp16(stB + (uint32_t)(fr * STR + fch) * 2, Bb);
        cp_commit();
    };

#pragma unroll
    for (int i = 0; i < NSTAGE - 1; i++) issue(i);

    for (int it = 0; it < 256; it++) {
        if (it + NSTAGE - 1 < 256) cp_wait<NSTAGE - 2>();
        else                       cp_wait<0>();
        __syncthreads();
        if (it + NSTAGE - 1 < 256) issue(it + NSTAGE - 1);

        const uint32_t stA = sbase + (uint32_t)(it & (NSTAGE - 1)) * STAGE_B;
        const uint32_t stB = stA + A_TILE_H * 2;

#pragma unroll
        for (int ks = 0; ks < 2; ks++) {
            const int k0 = ks * 16;
            uint32_t a[4][4], bf[4];
#pragma unroll
            for (int mt = 0; mt < 4; mt++) {
                int row  = wm * 64 + mt * 16 + (lane & 15);
                int colh = k0 + ((lane >> 4) << 3);
                ldsm4(a[mt], stA + (uint32_t)(row * STR + colh) * 2);
            }
            {
                int sub  = lane >> 3;
                int n    = wn * 16 + (sub >> 1) * 8 + (lane & 7);
                int colh = k0 + ((sub & 1) << 3);
                ldsm4(bf, stB + (uint32_t)(n * STR + colh) * 2);
            }
#pragma unroll
            for (int mt = 0; mt < 4; mt++)
#pragma unroll
                for (int nt = 0; nt < 2; nt++)
                    mma_f16(&acc[(mt * 2 + nt) * 4], a[mt], &bf[nt * 2]);
        }

        if ((it & 15) == 15) {
            // fold coef into y accumulators: w_pq = Art[p][r] * Art[q][c]
            const int coef = it >> 4;
            const int r = coef >> 2, c = coef & 3;
            const float wr0 = (r < 3) ? 1.f : 0.f;
            const float wr1 = (r == 0) ? 0.f : ((r == 1) ? 1.f : -1.f);
            const float wc0 = (c < 3) ? 1.f : 0.f;
            const float wc1 = (c == 0) ? 0.f : ((c == 1) ? 1.f : -1.f);
            const float s00 = wr0 * wc0, s01 = wr0 * wc1;
            const float s10 = wr1 * wc0, s11 = wr1 * wc1;
#pragma unroll
            for (int i = 0; i < 32; i++) {
                float v = acc[i];
                y00[i] = fmaf(s00, v, y00[i]);
                y01[i] = fmaf(s01, v, y01[i]);
                y10[i] = fmaf(s10, v, y10[i]);
                y11[i] = fmaf(s11, v, y11[i]);
                acc[i] = 0.f;
            }
        }
    }

    // ---- epilogue: demodulate + scatter 2x2 pixels per tile ----
    const int b = n0 >> 10;                // 64 | 1024 -> constant per CTA
#pragma unroll
    for (int mt = 0; mt < 4; mt++) {
        const int oc_r = oc0 + wm * 64 + mt * 16 + qr;
        const float rdA = g_rdenom[b * C_ + oc_r];
        const float rdB = g_rdenom[b * C_ + oc_r + 8];
#pragma unroll
        for (int nt = 0; nt < 2; nt++) {
            const int nb = n0 + wn * 16 + nt * 8 + qc * 2;   // tile pair nb, nb+1
            const int t  = nb & 1023;
            const int ty = t >> 5, tx = t & 31;
            const int i0 = (mt * 2 + nt) * 4;
            float* pA = out + ((size_t)(b * C_ + oc_r)) * HW_ + (2 * ty) * W64 + 2 * tx;
            *(float4*)pA = make_float4(y00[i0] * rdA, y01[i0] * rdA,
                                       y00[i0 + 1] * rdA, y01[i0 + 1] * rdA);
            *(float4*)(pA + W64) = make_float4(y10[i0] * rdA, y11[i0] * rdA,
                                               y10[i0 + 1] * rdA, y11[i0 + 1] * rdA);
            float* pB = out + ((size_t)(b * C_ + oc_r + 8)) * HW_ + (2 * ty) * W64 + 2 * tx;
            *(float4*)pB = make_float4(y00[i0 + 2] * rdB, y01[i0 + 2] * rdB,
                                       y00[i0 + 3] * rdB, y01[i0 + 3] * rdB);
            *(float4*)(pB + W64) = make_float4(y10[i0 + 2] * rdB, y11[i0 + 2] * rdB,
                                               y10[i0 + 3] * rdB, y11[i0 + 3] * rdB);
        }
    }
}

// ---------------- launch ----------------
extern "C" void kernel_launch(void* const* d_in, const int* in_sizes, int n_in,
                              void* d_out, int out_size) {
    const float* x  = (const float*)d_in[0];   // (16,512,64,64)
    const float* w  = (const float*)d_in[1];   // (16,512)
    const float* cw = (const float*)d_in[2];   // (512,512,3,3)
    const float* lw = (const float*)d_in[3];   // (512,512)
    const float* lb = (const float*)d_in[4];   // (512,)
    float* out = (float*)d_out;                // (16,512,64,64) fp32

    cudaFuncSetAttribute(wino_fused_kernel,
                         cudaFuncAttributeMaxDynamicSharedMemorySize, SMEM_BYTES);

    style_kernel<<<B_, C_>>>(w, lw, lb);
    s_kernel<<<C_, C_>>>(cw);
    rdenom_kernel<<<B_, C_>>>();
    wino_w_kernel<<<C_, C_>>>(cw);
    wino_x_kernel<<<dim3(32, C_ / 32, B_), 256>>>(x);
    wino_fused_kernel<<<dim3(C_ / 128, NT_ / 64), 256, SMEM_BYTES>>>(out);
}

// round 9
// speedup vs baseline: 1.2321x; 1.2321x over previous
#include <cuda_runtime.h>
#include <cuda_fp16.h>
#include <cstdint>

#define B_   16
#define C_   512
#define HW_  4096
#define W64  64
#define WD_  512
#define EPS_ 1e-6f
#define NT_  16384           // total Winograd tiles = B_ * 1024
#define NCF  16              // Winograd coefficients (4x4)

// ---------------- scratch (__device__ globals; no runtime alloc) ----------------
__device__ float  g_style[B_ * C_];
__device__ float  g_S[C_ * C_];
__device__ float  g_rdenom[B_ * C_];
__device__ __half g_U[(size_t)NCF * C_ * C_];        // (coef, oc, ic) fp16
__device__ __half g_V[(size_t)NCF * NT_ * C_];       // (coef, n, ic)  fp16
__device__ __half g_M[(size_t)NCF * C_ * NT_];       // (coef, oc, n)  fp16

// ---------------- helpers ----------------
__device__ __forceinline__ uint32_t smem_u32(const void* p) {
    uint32_t a;
    asm("{ .reg .u64 t; cvta.to.shared.u64 t, %1; cvt.u32.u64 %0, t; }" : "=r"(a) : "l"(p));
    return a;
}
__device__ __forceinline__ void cp16(uint32_t dst, const void* src) {
    asm volatile("cp.async.cg.shared.global [%0], [%1], 16;" :: "r"(dst), "l"(src));
}
template <int N>
__device__ __forceinline__ void cp_wait() {
    asm volatile("cp.async.wait_group %0;" :: "n"(N) : "memory");
}
__device__ __forceinline__ void cp_commit() {
    asm volatile("cp.async.commit_group;" ::: "memory");
}
__device__ __forceinline__ void ldsm4(uint32_t* r, uint32_t addr) {
    asm volatile("ldmatrix.sync.aligned.m8n8.x4.shared.b16 {%0,%1,%2,%3}, [%4];"
                 : "=r"(r[0]), "=r"(r[1]), "=r"(r[2]), "=r"(r[3]) : "r"(addr));
}
__device__ __forceinline__ void mma_f16(float* d, const uint32_t* a, const uint32_t* bf) {
    asm volatile(
        "mma.sync.aligned.m16n8k16.row.col.f32.f16.f16.f32 "
        "{%0,%1,%2,%3}, {%4,%5,%6,%7}, {%8,%9}, {%0,%1,%2,%3};"
        : "+f"(d[0]), "+f"(d[1]), "+f"(d[2]), "+f"(d[3])
        : "r"(a[0]), "r"(a[1]), "r"(a[2]), "r"(a[3]), "r"(bf[0]), "r"(bf[1]));
}

// ---------------- prologue: style / S / rdenom ----------------
__global__ void style_kernel(const float* __restrict__ w, const float* __restrict__ lw,
                             const float* __restrict__ lb) {
    __shared__ float ws[WD_];
    int b = blockIdx.x, o = threadIdx.x;
    ws[o] = w[b * WD_ + o];
    __syncthreads();
    const float* lwr = lw + (size_t)o * WD_;
    float acc = lb[o];
#pragma unroll 8
    for (int d = 0; d < WD_; d++) acc = fmaf(ws[d], lwr[d], acc);
    g_style[b * C_ + o] = acc;
}

__global__ void s_kernel(const float* __restrict__ cw) {
    int o = blockIdx.x, i = threadIdx.x;
    const float* p = cw + ((size_t)o * C_ + i) * 9;
    float s = 0.f;
#pragma unroll
    for (int k = 0; k < 9; k++) { float v = p[k]; s = fmaf(v, v, s); }
    g_S[o * C_ + i] = s;
}

__global__ void rdenom_kernel() {
    __shared__ float st2[C_];
    int b = blockIdx.x, o = threadIdx.x;
    float s = g_style[b * C_ + o];
    st2[o] = s * s;
    __syncthreads();
    const float* Sr = g_S + (size_t)o * C_;
    float acc = EPS_;
#pragma unroll 8
    for (int i = 0; i < C_; i++) acc = fmaf(Sr[i], st2[i], acc);
    g_rdenom[b * C_ + o] = rsqrtf(acc);
}

// ---------------- Winograd weight transform: U = G g G^T ----------------
__global__ void wino_w_kernel(const float* __restrict__ cw) {
    int o = blockIdx.x, i = threadIdx.x;
    const float* g = cw + ((size_t)o * C_ + i) * 9;
    float q[3][3];
#pragma unroll
    for (int r = 0; r < 3; r++)
#pragma unroll
        for (int c = 0; c < 3; c++) q[r][c] = g[r * 3 + c];
    float t[4][3];
#pragma unroll
    for (int c = 0; c < 3; c++) {
        t[0][c] = q[0][c];
        t[1][c] = 0.5f * (q[0][c] + q[1][c] + q[2][c]);
        t[2][c] = 0.5f * (q[0][c] - q[1][c] + q[2][c]);
        t[3][c] = q[2][c];
    }
#pragma unroll
    for (int r = 0; r < 4; r++) {
        float u0 = t[r][0];
        float u1 = 0.5f * (t[r][0] + t[r][1] + t[r][2]);
        float u2 = 0.5f * (t[r][0] - t[r][1] + t[r][2]);
        float u3 = t[r][2];
        g_U[((size_t)(r * 4 + 0) * C_ + o) * C_ + i] = __float2half_rn(u0);
        g_U[((size_t)(r * 4 + 1) * C_ + o) * C_ + i] = __float2half_rn(u1);
        g_U[((size_t)(r * 4 + 2) * C_ + o) * C_ + i] = __float2half_rn(u2);
        g_U[((size_t)(r * 4 + 3) * C_ + o) * C_ + i] = __float2half_rn(u3);
    }
}

// ---------------- Winograd input transform: V = B^T d B (style folded) ----------------
__global__ void __launch_bounds__(256)
wino_x_kernel(const float* __restrict__ x) {
    __shared__ float xs[4][32][71];
    const int b = blockIdx.z, chg = blockIdx.y * 32, ty = blockIdx.x;
    const int tid = threadIdx.x;

    for (int idx = tid; idx < 4 * 32 * 68; idx += 256) {
        int r   = idx / (32 * 68);
        int rem = idx % (32 * 68);
        int ch  = rem / 68;
        int col = rem % 68;
        if (col < 66) {
            int y  = ty * 2 - 1 + r;
            int xg = col - 1;
            float v = 0.f;
            if ((unsigned)y < W64 && (unsigned)xg < W64)
                v = x[((size_t)(b * C_ + chg + ch)) * HW_ + y * W64 + xg];
            xs[r][ch][col] = v;
        }
    }
    __syncthreads();

    const int tx  = tid >> 3;          // 0..31 tile col
    const int ch4 = (tid & 7) * 4;     // 0,4,...,28
    const int n   = b * 1024 + ty * 32 + tx;

    unsigned short hs[NCF][4];
#pragma unroll
    for (int cc = 0; cc < 4; cc++) {
        const int ch = ch4 + cc;
        const float st = g_style[b * C_ + chg + ch];
        float d[4][4];
#pragma unroll
        for (int r = 0; r < 4; r++)
#pragma unroll
            for (int c = 0; c < 4; c++) d[r][c] = xs[r][ch][2 * tx + c];
        float wv[4][4];
#pragma unroll
        for (int c = 0; c < 4; c++) {
            wv[0][c] = d[0][c] - d[2][c];
            wv[1][c] = d[1][c] + d[2][c];
            wv[2][c] = d[2][c] - d[1][c];
            wv[3][c] = d[1][c] - d[3][c];
        }
#pragma unroll
        for (int r = 0; r < 4; r++) {
            float v0 = wv[r][0] - wv[r][2];
            float v1 = wv[r][1] + wv[r][2];
            float v2 = wv[r][2] - wv[r][1];
            float v3 = wv[r][1] - wv[r][3];
            hs[r * 4 + 0][cc] = __half_as_ushort(__float2half_rn(v0 * st));
            hs[r * 4 + 1][cc] = __half_as_ushort(__float2half_rn(v1 * st));
            hs[r * 4 + 2][cc] = __half_as_ushort(__float2half_rn(v2 * st));
            hs[r * 4 + 3][cc] = __half_as_ushort(__float2half_rn(v3 * st));
        }
    }
#pragma unroll
    for (int c = 0; c < NCF; c++) {
        uint2 val;
        val.x = (uint32_t)hs[c][0] | ((uint32_t)hs[c][1] << 16);
        val.y = (uint32_t)hs[c][2] | ((uint32_t)hs[c][3] << 16);
        *(uint2*)(g_V + ((size_t)c * NT_ + n) * C_ + chg + ch4) = val;
    }
}

// ---------------- Winograd GEMM: M[coef] = U[coef] @ V[coef]^T (fp16 out) ----------------
// CTA 128 oc x 128 n; K = 512 (16 chunks of 32). 8 warps: (wm2 x wn4), warp tile
// 64x32 = 4x4 m16n8k16 tiles x 2 ksteps. NSTAGE=4 ring, ONE sync per iteration.
#define STR    40
#define TILE_H (128 * STR)                 // 5120 halves per tile
#define STAGE_B (2 * TILE_H * 2)           // A + B per stage = 20480 bytes
#define NSTAGE 4
#define SMEM_BYTES (NSTAGE * STAGE_B)      // 81920

__global__ void __launch_bounds__(256, 2)
wino_gemm_kernel() {
    extern __shared__ __half smh[];
    const int tid  = threadIdx.x;
    const int coef = blockIdx.z;
    const int oc0  = blockIdx.y * 128;
    const int n0   = blockIdx.x * 128;
    const int lane = tid & 31;
    const int wrp  = tid >> 5;
    const int wm   = wrp & 1;
    const int wn   = wrp >> 1;
    const int qr   = lane >> 2;
    const int qc   = lane & 3;
    const int fr   = tid >> 2;             // 0..63
    const int fch  = (tid & 3) * 8;

    const __half* Ag = g_U + ((size_t)coef * C_ + oc0) * C_;
    const __half* Bg = g_V + ((size_t)coef * NT_ + n0) * C_;
    const uint32_t sbase = smem_u32(smh);

    float acc[4][4][4];
#pragma unroll
    for (int mt = 0; mt < 4; mt++)
#pragma unroll
        for (int nt = 0; nt < 4; nt++)
#pragma unroll
            for (int r = 0; r < 4; r++) acc[mt][nt][r] = 0.f;

    auto issue = [&](int it) {
        const int s   = it & (NSTAGE - 1);
        const int ci0 = it << 5;
        const uint32_t stA = sbase + (uint32_t)s * STAGE_B;
        const uint32_t stB = stA + TILE_H * 2;
        const __half* Ab = Ag + (size_t)fr * C_ + ci0 + fch;
        const __half* Bb = Bg + (size_t)fr * C_ + ci0 + fch;
        cp16(stA + (uint32_t)(fr * STR + fch) * 2, Ab);
        cp16(stA + (uint32_t)((fr + 64) * STR + fch) * 2, Ab + (size_t)64 * C_);
        cp16(stB + (uint32_t)(fr * STR + fch) * 2, Bb);
        cp16(stB + (uint32_t)((fr + 64) * STR + fch) * 2, Bb + (size_t)64 * C_);
        cp_commit();
    };

#pragma unroll
    for (int i = 0; i < NSTAGE - 1; i++) issue(i);

    for (int it = 0; it < 16; it++) {
        if (it + NSTAGE - 1 < 16) cp_wait<NSTAGE - 2>();
        else                      cp_wait<0>();
        __syncthreads();
        if (it + NSTAGE - 1 < 16) issue(it + NSTAGE - 1);

        const uint32_t stA = sbase + (uint32_t)(it & (NSTAGE - 1)) * STAGE_B;
        const uint32_t stB = stA + TILE_H * 2;

#pragma unroll
        for (int ks = 0; ks < 2; ks++) {
            const int k0 = ks * 16;
            uint32_t a[4][4], bf[2][4];
#pragma unroll
            for (int mt = 0; mt < 4; mt++) {
                int row  = wm * 64 + mt * 16 + (lane & 15);
                int colh = k0 + ((lane >> 4) << 3);
                ldsm4(a[mt], stA + (uint32_t)(row * STR + colh) * 2);
            }
#pragma unroll
            for (int pp = 0; pp < 2; pp++) {
                int sub  = lane >> 3;
                int n    = wn * 32 + (pp * 2 + (sub >> 1)) * 8 + (lane & 7);
                int colh = k0 + ((sub & 1) << 3);
                ldsm4(bf[pp], stB + (uint32_t)(n * STR + colh) * 2);
            }
#pragma unroll
            for (int mt = 0; mt < 4; mt++) {
#pragma unroll
                for (int nt = 0; nt < 4; nt++)
                    mma_f16(acc[mt][nt], a[mt], &bf[nt >> 1][(nt & 1) * 2]);
            }
        }
    }

    // epilogue: store M[coef][oc][n] as fp16
#pragma unroll
    for (int mt = 0; mt < 4; mt++) {
        const int oc_r = oc0 + wm * 64 + mt * 16 + qr;
        __half* o0 = g_M + ((size_t)coef * C_ + oc_r) * NT_ + n0 + wn * 32 + qc * 2;
        __half* o1 = o0 + (size_t)8 * NT_;
#pragma unroll
        for (int nt = 0; nt < 4; nt++) {
            *(__half2*)(o0 + nt * 8) = __floats2half2_rn(acc[mt][nt][0], acc[mt][nt][1]);
            *(__half2*)(o1 + nt * 8) = __floats2half2_rn(acc[mt][nt][2], acc[mt][nt][3]);
        }
    }
}

// ---------------- inverse transform: Y = A^T M A, demodulate, store ----------------
__global__ void __launch_bounds__(256)
wino_inv_kernel(float* __restrict__ out) {
    const int n  = blockIdx.x * 256 + threadIdx.x;   // 0..16383
    const int oc = blockIdx.y;
    const int b  = n >> 10, t = n & 1023;
    const int ty = t >> 5, tx = t & 31;

    float m[16];
#pragma unroll
    for (int c = 0; c < NCF; c++)
        m[c] = __half2float(g_M[((size_t)c * C_ + oc) * NT_ + n]);

    float z0[4], z1[4];
#pragma unroll
    for (int k = 0; k < 4; k++) {
        z0[k] = m[k * 4 + 0] + m[k * 4 + 1] + m[k * 4 + 2];
        z1[k] = m[k * 4 + 1] - m[k * 4 + 2] - m[k * 4 + 3];
    }
    const float rd = g_rdenom[b * C_ + oc];
    float y00 = (z0[0] + z0[1] + z0[2]) * rd;
    float y01 = (z1[0] + z1[1] + z1[2]) * rd;
    float y10 = (z0[1] - z0[2] - z0[3]) * rd;
    float y11 = (z1[1] - z1[2] - z1[3]) * rd;

    float* op = out + ((size_t)(b * C_ + oc)) * HW_ + (ty * 2) * W64 + tx * 2;
    *(float2*)op          = make_float2(y00, y01);
    *(float2*)(op + W64)  = make_float2(y10, y11);
}

// ---------------- launch ----------------
extern "C" void kernel_launch(void* const* d_in, const int* in_sizes, int n_in,
                              void* d_out, int out_size) {
    const float* x  = (const float*)d_in[0];   // (16,512,64,64)
    const float* w  = (const float*)d_in[1];   // (16,512)
    const float* cw = (const float*)d_in[2];   // (512,512,3,3)
    const float* lw = (const float*)d_in[3];   // (512,512)
    const float* lb = (const float*)d_in[4];   // (512,)
    float* out = (float*)d_out;                // (16,512,64,64) fp32

    cudaFuncSetAttribute(wino_gemm_kernel,
                         cudaFuncAttributeMaxDynamicSharedMemorySize, SMEM_BYTES);

    style_kernel<<<B_, C_>>>(w, lw, lb);
    s_kernel<<<C_, C_>>>(cw);
    rdenom_kernel<<<B_, C_>>>();
    wino_w_kernel<<<C_, C_>>>(cw);
    wino_x_kernel<<<dim3(32, C_ / 32, B_), 256>>>(x);
    wino_gemm_kernel<<<dim3(NT_ / 128, C_ / 128, NCF), 256, SMEM_BYTES>>>();
    wino_inv_kernel<<<dim3(NT_ / 256, C_), 256>>>(out);
}